// round 12
// baseline (speedup 1.0000x reference)
#include <cuda_runtime.h>

#define FULL 0xffffffffu

// Per-row compute: attention scores vs rel rows (lane = neighbor),
// softmax over lanes, neighbor aggregation + matvec (lane = dim).
template<bool SHARED_NV>
__device__ __forceinline__ float row_core(
    float sv, int r2,
    const float (&nvreg)[32], const float* __restrict__ nv_sh,
    const float* __restrict__ s_rel,
    const float* __restrict__ s_W,
    const float* __restrict__ s_bv,
    int lane, bool last)
{
    // scores: lane n computes dot(sv, rel_emb[r2_n])
    float s = 0.f;
    const float* rr = s_rel + r2 * 33;
    #pragma unroll
    for (int d = 0; d < 32; d++)
        s = fmaf(__shfl_sync(FULL, sv, d), rr[d], s);

    // softmax over the 32 neighbors (lanes)
    float mx = s;
    #pragma unroll
    for (int o = 16; o; o >>= 1) mx = fmaxf(mx, __shfl_xor_sync(FULL, mx, o));
    float e = __expf(s - mx);
    float sum = e;
    #pragma unroll
    for (int o = 16; o; o >>= 1) sum += __shfl_xor_sync(FULL, sum, o);
    float p = e / sum;

    // aggregate: lane d accumulates sum_n p_n * nv[n][d]
    float agg = 0.f;
    #pragma unroll
    for (int n = 0; n < 32; n++) {
        float pn = __shfl_sync(FULL, p, n);
        float nv = SHARED_NV ? nv_sh[n * 32 + lane] : nvreg[n];
        agg = fmaf(pn, nv, agg);
    }

    // (sv + agg) @ W + b
    float x = sv + agg;
    float y = s_bv[lane];
    #pragma unroll
    for (int k = 0; k < 32; k++)
        y = fmaf(__shfl_sync(FULL, x, k), s_W[k * 32 + lane], y);

    if (last) return tanhf(y);
    return 1.f / (1.f + __expf(-y));   // sigmoid
}

__global__ __launch_bounds__(288) void kgcn_kernel(
    const int*   __restrict__ drug,      // [B]
    const int*   __restrict__ adj_ent,   // [NUM_ENT, 32]
    const int*   __restrict__ adj_rel,   // [NUM_ENT, 32]
    const float* __restrict__ ent_emb,   // [NUM_ENT, 32]
    const float* __restrict__ rel_emb,   // [64, 32]
    const float* __restrict__ Wm,        // [32, 32]
    const float* __restrict__ bv,        // [32]
    float*       __restrict__ out)       // [B, 32]
{
    __shared__ float s_rel[64 * 33];   // padded rows: bank = (r + d) & 31
    __shared__ float s_W[32 * 32];
    __shared__ float s_b[32];
    __shared__ int   s_e1[32];
    __shared__ int   s_r0[32];
    __shared__ int   s_drug;
    __shared__ float s_h1[32 * 32];    // iter0 hop1 outputs
    __shared__ float s_h0[32];         // iter0 hop0 output

    const int b    = blockIdx.x;
    const int tid  = threadIdx.x;
    const int w    = tid >> 5;
    const int lane = tid & 31;

    for (int i = tid; i < 64 * 32; i += 288)
        s_rel[(i >> 5) * 33 + (i & 31)] = rel_emb[i];
    for (int i = tid; i < 32 * 32; i += 288)
        s_W[i] = Wm[i];
    if (tid < 32) {
        s_b[tid] = bv[tid];
        int dr = drug[b];
        if (tid == 0) s_drug = dr;
        s_e1[tid] = adj_ent[dr * 32 + tid];   // entities[1][b, :]
        s_r0[tid] = adj_rel[dr * 32 + tid];   // relations[0][b, :]
    }
    __syncthreads();

    // rows 0..31 = iter0 hop1 (one row per hop-1 entity);
    // row 32     = iter0 hop0 (drug's own row). One warp per row.
    float dummy[32];
    for (int r = w; r < 33; r += 9) {
        int self_e, e2, r2;
        if (r < 32) {
            self_e = s_e1[r];
            e2 = adj_ent[self_e * 32 + lane];   // lane = n: neighbor entity
            r2 = adj_rel[self_e * 32 + lane];   // lane = n: neighbor relation
        } else {
            self_e = s_drug;
            e2 = s_e1[lane];
            r2 = s_r0[lane];
        }
        float sv = ent_emb[self_e * 32 + lane];  // lane = d

        // prefetch neighbor embeddings (lane = d) to hide L2 latency
        float nvreg[32];
        #pragma unroll
        for (int n = 0; n < 32; n++) {
            int en = __shfl_sync(FULL, e2, n);
            nvreg[n] = ent_emb[en * 32 + lane];
        }

        float h = row_core<false>(sv, r2, nvreg, nullptr,
                                  s_rel, s_W, s_b, lane, false);
        if (r < 32) s_h1[r * 32 + lane] = h;
        else        s_h0[lane] = h;
    }
    __syncthreads();

    // iter1 hop0: sv = h0, neighbors = h1 rows, rels = r0, tanh
    if (w == 0) {
        float sv = s_h0[lane];
        int   r2 = s_r0[lane];
        float h = row_core<true>(sv, r2, dummy, s_h1,
                                 s_rel, s_W, s_b, lane, true);
        out[b * 32 + lane] = h;
    }
}

extern "C" void kernel_launch(void* const* d_in, const int* in_sizes, int n_in,
                              void* d_out, int out_size) {
    const int*   drug    = (const int*)d_in[0];
    const int*   adj_ent = (const int*)d_in[1];
    const int*   adj_rel = (const int*)d_in[2];
    const float* ent_emb = (const float*)d_in[3];
    const float* rel_emb = (const float*)d_in[4];
    const float* Wm      = (const float*)d_in[5];
    const float* bv      = (const float*)d_in[6];
    float*       out     = (float*)d_out;
    const int B = in_sizes[0];
    kgcn_kernel<<<B, 288>>>(drug, adj_ent, adj_rel, ent_emb, rel_emb, Wm, bv, out);
}

// round 13
// speedup vs baseline: 1.1633x; 1.1633x over previous
#include <cuda_runtime.h>

#define FULL 0xffffffffu

__global__ __launch_bounds__(288) void kgcn_kernel(
    const int*   __restrict__ drug,      // [B]
    const int*   __restrict__ adj_ent,   // [NUM_ENT, 32]
    const int*   __restrict__ adj_rel,   // [NUM_ENT, 32]
    const float* __restrict__ ent_emb,   // [NUM_ENT, 32]
    const float* __restrict__ rel_emb,   // [64, 32]
    const float* __restrict__ Wm,        // [32, 32]
    const float* __restrict__ bv,        // [32]
    float*       __restrict__ out)       // [B, 32]
{
    __shared__ float s_rel[64 * 33];   // padded: bank = (r + d) & 31
    __shared__ float s_W[32 * 32];
    __shared__ float s_b[32];
    __shared__ int   s_e1[32];
    __shared__ int   s_r0[32];
    __shared__ int   s_drug;
    __shared__ float s_h1[32 * 32];    // iter0 hop1 outputs (lane = d)
    __shared__ float s_h0[32];         // iter0 hop0 output
    __shared__ __align__(16) float s_xw[9][32];  // per-warp sv/x scratch

    const int b    = blockIdx.x;
    const int tid  = threadIdx.x;
    const int w    = tid >> 5;
    const int lane = tid & 31;
    const int a    = lane >> 3;        // chunk layout: neighbor-group
    const int c    = lane & 7;         // chunk layout: dim-chunk (dims 4c..4c+3)

    for (int i = tid; i < 64 * 32; i += 288)
        s_rel[(i >> 5) * 33 + (i & 31)] = rel_emb[i];
    for (int i = tid; i < 32 * 32; i += 288)
        s_W[i] = Wm[i];
    if (tid < 32) {
        s_b[tid] = bv[tid];
        int dr = drug[b];
        if (tid == 0) s_drug = dr;
        s_e1[tid] = adj_ent[dr * 32 + tid];   // entities[1][b, :]
        s_r0[tid] = adj_rel[dr * 32 + tid];   // relations[0][b, :]
    }
    __syncthreads();

    // rows 0..31 = iter0 hop1; row 32 = iter0 hop0. One warp per row.
    for (int r = w; r < 33; r += 9) {
        int self_e, e2, r2;
        if (r < 32) {
            self_e = s_e1[r];
            e2 = adj_ent[self_e * 32 + lane];   // lane = n
            r2 = adj_rel[self_e * 32 + lane];   // lane = n
        } else {
            self_e = s_drug;
            e2 = s_e1[lane];
            r2 = s_r0[lane];
        }
        float sv = ent_emb[self_e * 32 + lane];  // lane = d
        s_xw[w][lane] = sv;

        // gather neighbor embeddings in chunk layout:
        // nv4[i] = dims [4c..4c+3] of neighbor (4i + a). 8 LDG.128, coalesced.
        float4 nv4[8];
        #pragma unroll
        for (int i = 0; i < 8; i++) {
            int en = __shfl_sync(FULL, e2, 4 * i + a);
            nv4[i] = *reinterpret_cast<const float4*>(ent_emb + en * 32 + 4 * c);
        }

        // scores: lane n computes dot(sv, rel_emb[r2_n])
        float s = 0.f;
        const float* rr = s_rel + r2 * 33;
        #pragma unroll
        for (int d = 0; d < 32; d++)
            s = fmaf(__shfl_sync(FULL, sv, d), rr[d], s);

        // softmax over neighbors (lanes)
        float mx = s;
        #pragma unroll
        for (int o = 16; o; o >>= 1) mx = fmaxf(mx, __shfl_xor_sync(FULL, mx, o));
        float e = __expf(s - mx);
        float sum = e;
        #pragma unroll
        for (int o = 16; o; o >>= 1) sum += __shfl_xor_sync(FULL, sum, o);
        float p = e / sum;

        // aggregate in chunk layout: partial over this lane's 8 neighbors
        float4 ps = make_float4(0.f, 0.f, 0.f, 0.f);
        #pragma unroll
        for (int i = 0; i < 8; i++) {
            float pn = __shfl_sync(FULL, p, 4 * i + a);
            ps.x = fmaf(pn, nv4[i].x, ps.x);
            ps.y = fmaf(pn, nv4[i].y, ps.y);
            ps.z = fmaf(pn, nv4[i].z, ps.z);
            ps.w = fmaf(pn, nv4[i].w, ps.w);
        }
        // reduce over the 4 lanes sharing chunk c (lanes c, c+8, c+16, c+24)
        #pragma unroll
        for (int o = 8; o <= 16; o <<= 1) {
            ps.x += __shfl_xor_sync(FULL, ps.x, o);
            ps.y += __shfl_xor_sync(FULL, ps.y, o);
            ps.z += __shfl_xor_sync(FULL, ps.z, o);
            ps.w += __shfl_xor_sync(FULL, ps.w, o);
        }

        // x = sv + agg, staged to shared (lanes 0..7 cover all 8 chunks)
        __syncwarp();
        if (lane < 8) {
            float4 sv4 = reinterpret_cast<float4*>(s_xw[w])[lane];
            sv4.x += ps.x; sv4.y += ps.y; sv4.z += ps.z; sv4.w += ps.w;
            reinterpret_cast<float4*>(s_xw[w])[lane] = sv4;
        }
        __syncwarp();

        // matvec: lane = output dim; x broadcast via 8 uniform LDS.128
        float y = s_b[lane];
        #pragma unroll
        for (int i = 0; i < 8; i++) {
            float4 x4 = reinterpret_cast<const float4*>(s_xw[w])[i];
            y = fmaf(x4.x, s_W[(4 * i + 0) * 32 + lane], y);
            y = fmaf(x4.y, s_W[(4 * i + 1) * 32 + lane], y);
            y = fmaf(x4.z, s_W[(4 * i + 2) * 32 + lane], y);
            y = fmaf(x4.w, s_W[(4 * i + 3) * 32 + lane], y);
        }
        float h = 1.f / (1.f + __expf(-y));   // sigmoid (iter0)
        if (r < 32) s_h1[r * 32 + lane] = h;
        else        s_h0[lane] = h;
    }
    __syncthreads();

    // iter1 hop0: sv = h0, neighbors = h1 rows (shared), rels = r0, tanh.
    // One row per CTA — keep the simple scalar path.
    if (w == 0) {
        float sv = s_h0[lane];
        int   r2 = s_r0[lane];
        float s = 0.f;
        const float* rr = s_rel + r2 * 33;
        #pragma unroll
        for (int d = 0; d < 32; d++)
            s = fmaf(__shfl_sync(FULL, sv, d), rr[d], s);
        float mx = s;
        #pragma unroll
        for (int o = 16; o; o >>= 1) mx = fmaxf(mx, __shfl_xor_sync(FULL, mx, o));
        float e = __expf(s - mx);
        float sum = e;
        #pragma unroll
        for (int o = 16; o; o >>= 1) sum += __shfl_xor_sync(FULL, sum, o);
        float p = e / sum;
        float agg = 0.f;
        #pragma unroll
        for (int n = 0; n < 32; n++) {
            float pn = __shfl_sync(FULL, p, n);
            agg = fmaf(pn, s_h1[n * 32 + lane], agg);
        }
        float x = sv + agg;
        float y = s_b[lane];
        #pragma unroll
        for (int k = 0; k < 32; k++)
            y = fmaf(__shfl_sync(FULL, x, k), s_W[k * 32 + lane], y);
        out[b * 32 + lane] = tanhf(y);
    }
}

extern "C" void kernel_launch(void* const* d_in, const int* in_sizes, int n_in,
                              void* d_out, int out_size) {
    const int*   drug    = (const int*)d_in[0];
    const int*   adj_ent = (const int*)d_in[1];
    const int*   adj_rel = (const int*)d_in[2];
    const float* ent_emb = (const float*)d_in[3];
    const float* rel_emb = (const float*)d_in[4];
    const float* Wm      = (const float*)d_in[5];
    const float* bv      = (const float*)d_in[6];
    float*       out     = (float*)d_out;
    const int B = in_sizes[0];
    kgcn_kernel<<<B, 288>>>(drug, adj_ent, adj_rel, ent_emb, rel_emb, Wm, bv, out);
}